// round 1
// baseline (speedup 1.0000x reference)
#include <cuda_runtime.h>
#include <cuda_bf16.h>
#include <stdint.h>

// Problem constants: N=96 anchors, D=64 dims, C=30 classes, K_DELTA=2.0
#define NN 96
#define DD 64
#define CC 30

// Scratch (no allocations allowed -> __device__ globals)
__device__ float    g_mat[NN * NN];          // -(x_norm @ x_norm^T)
__device__ unsigned g_cmask[NN * NN * 4];    // c[i,p,:] as 96-bit mask (3 words + pad)

// ---------------------------------------------------------------------------
// Kernel 1: cosine-distance matrix. One block per row i.
// smem rows padded to 65 floats -> conflict-free column access.
// ---------------------------------------------------------------------------
__global__ __launch_bounds__(128) void mat_kernel(const float* __restrict__ logits) {
    __shared__ float sx[NN * 65];
    __shared__ float rn[NN];
    const int tid = threadIdx.x;
    const int bid = blockIdx.x;

    for (int t = tid; t < NN * DD; t += 128)
        sx[(t >> 6) * 65 + (t & 63)] = logits[t];
    __syncthreads();

    if (tid < NN) {
        float s = 0.f;
        #pragma unroll
        for (int d = 0; d < DD; d++) { float v = sx[tid * 65 + d]; s += v * v; }
        rn[tid] = rsqrtf(s);
    }
    __syncthreads();

    if (tid < NN) {
        float acc = 0.f;
        #pragma unroll
        for (int d = 0; d < DD; d++) acc += sx[bid * 65 + d] * sx[tid * 65 + d];
        g_mat[bid * NN + tid] = -acc * rn[bid] * rn[tid];
    }
}

// ---------------------------------------------------------------------------
// Kernel 2 (single block, 1024 thr): label masks, epsilon, c-bitmask.
// ---------------------------------------------------------------------------
__global__ __launch_bounds__(1024) void prep_kernel(const float* __restrict__ labels) {
    __shared__ float    slab[NN * CC];
    __shared__ unsigned s_smask[NN * 3];   // sames (diag zeroed)
    __shared__ unsigned s_dmask[NN * 3];   // diffs (= !sames_raw, incl. diag)
    __shared__ float    s_rnum[NN], s_rq[NN];
    __shared__ float    s_eps;

    const int tid  = threadIdx.x;
    const int warp = tid >> 5;
    const int lane = tid & 31;

    for (int t = tid; t < NN * CC; t += 1024) slab[t] = labels[t];
    for (int t = tid; t < NN * 3; t += 1024) { s_smask[t] = 0u; s_dmask[t] = 0u; }
    __syncthreads();

    // sames_raw[i,j] = (labels_i . labels_j) > 0
    for (int t = tid; t < NN * NN; t += 1024) {
        int i = t / NN, j = t - i * NN;
        float acc = 0.f;
        #pragma unroll
        for (int c = 0; c < CC; c++) acc += slab[i * CC + c] * slab[j * CC + c];
        if (acc > 0.f) {
            if (i != j) atomicOr(&s_smask[i * 3 + (j >> 5)], 1u << (j & 31));
        } else {
            atomicOr(&s_dmask[i * 3 + (j >> 5)], 1u << (j & 31));
        }
    }
    __syncthreads();

    // Per-row reductions for epsilon:
    //   num_i = (S-1)*(S*mdsum - msum_s*dsum),  q_i = S*(S-1)/2 * dsum
    for (int i = warp; i < NN; i += 32) {
        float S = 0.f, ds = 0.f, ms = 0.f, md = 0.f;
        #pragma unroll
        for (int jj = 0; jj < 3; jj++) {
            int j = jj * 32 + lane;
            float mv = g_mat[i * NN + j];
            if ((s_smask[i * 3 + jj] >> lane) & 1u) { S += 1.f; ms += mv; }
            if ((s_dmask[i * 3 + jj] >> lane) & 1u) { ds += 1.f; md += mv; }
        }
        #pragma unroll
        for (int o = 16; o; o >>= 1) {
            S  += __shfl_xor_sync(0xffffffffu, S,  o);
            ds += __shfl_xor_sync(0xffffffffu, ds, o);
            ms += __shfl_xor_sync(0xffffffffu, ms, o);
            md += __shfl_xor_sync(0xffffffffu, md, o);
        }
        if (lane == 0) {
            s_rnum[i] = (S - 1.f) * (S * md - ms * ds);
            s_rq[i]   = 0.5f * S * (S - 1.f) * ds;
        }
    }
    __syncthreads();

    if (tid == 0) {   // deterministic serial reduce
        float num = 0.f, q = 0.f;
        for (int i = 0; i < NN; i++) { num += s_rnum[i]; q += s_rq[i]; }
        float mean_delta = num / fmaxf(2.f * q, 1.f);
        s_eps = fmaxf(mean_delta * 0.5f, 0.f);   // relu(mean_delta / K_DELTA)
    }
    __syncthreads();
    const float eps = s_eps;

    // c[i,p,n] = sames[i,p] & diffs[i,n] & (0 < mat[i,n]-mat[i,p] <= eps)
    // built as 96-bit mask via warp ballots (one warp per (i,p) pair).
    for (int pid = warp; pid < NN * NN; pid += 32) {
        int i = pid / NN, p = pid - i * NN;
        unsigned sp = (s_smask[i * 3 + (p >> 5)] >> (p & 31)) & 1u;
        float matp = g_mat[i * NN + p];
        #pragma unroll
        for (int wd = 0; wd < 3; wd++) {
            float m = g_mat[i * NN + wd * 32 + lane] - matp;
            bool cc = sp && (((s_dmask[i * 3 + wd] >> lane) & 1u) != 0u)
                         && (m > 0.f) && (m <= eps);
            unsigned b = __ballot_sync(0xffffffffu, cc);
            if (lane == 0) g_cmask[pid * 4 + wd] = b;
        }
        if (lane == 0) g_cmask[pid * 4 + 3] = 0u;
    }
}

// ---------------------------------------------------------------------------
// Kernel 3: the 340 MB writer. One float4 (4 n-values) per thread,
// flat index -> perfectly coalesced stores.
//   total float4 = 96^4/4 = 21,233,664 = 82944 blocks * 256 threads
// ---------------------------------------------------------------------------
__global__ __launch_bounds__(256) void write_kernel(float4* __restrict__ out) {
    unsigned idx = blockIdx.x * 256u + threadIdx.x;
    unsigned n4  = idx % 24u;          // which float4 chunk of the n-row
    unsigned r   = idx / 24u;          // ((i*96)+j)*96 + k
    unsigned k   = r % 96u;
    unsigned r2  = r / 96u;            // i*96 + j
    unsigned j   = r2 % 96u;

    float4 v = make_float4(0.f, 0.f, 0.f, 0.f);
    if (j < k) {
        unsigned wd = n4 >> 3;                       // 96 bits = 3 words
        unsigned cA = g_cmask[(r2 << 2) + wd];       // c[i,j,:]
        unsigned cB = g_cmask[((r2 - j + k) << 2) + wd]; // c[i,k,:]
        unsigned w  = cA & cB;
        unsigned b  = w >> ((n4 & 7u) * 4u);
        const unsigned ONEF = 0x3f800000u;
        v.x = __uint_as_float(ONEF & (0u - (b & 1u)));
        v.y = __uint_as_float(ONEF & (0u - ((b >> 1) & 1u)));
        v.z = __uint_as_float(ONEF & (0u - ((b >> 2) & 1u)));
        v.w = __uint_as_float(ONEF & (0u - ((b >> 3) & 1u)));
    }
    out[idx] = v;
}

// ---------------------------------------------------------------------------
extern "C" void kernel_launch(void* const* d_in, const int* in_sizes, int n_in,
                              void* d_out, int out_size) {
    const float* logits = (const float*)d_in[0];   // [96,64]
    const float* labels = (const float*)d_in[1];   // [96,30]

    mat_kernel<<<NN, 128>>>(logits);
    prep_kernel<<<1, 1024>>>(labels);
    write_kernel<<<82944, 256>>>((float4*)d_out);
}

// round 2
// speedup vs baseline: 2.1707x; 2.1707x over previous
#include <cuda_runtime.h>
#include <cuda_bf16.h>
#include <stdint.h>

#define NN 96
#define DD 64
#define CC 30

// Scratch (__device__ globals; no allocation allowed)
__device__ float    g_mat[NN * NN];
__device__ unsigned g_smask[NN * 3];
__device__ unsigned g_dmask[NN * 3];
__device__ float    g_eps;
__device__ unsigned g_cmask[NN * NN * 4];   // 96-bit mask per (i,p), stride 4 words

// ---------------------------------------------------------------------------
// K1: blocks 0..95 -> cosine mat row i ; block 96 -> label masks.
// ---------------------------------------------------------------------------
__global__ __launch_bounds__(256) void k1_mat_labels(const float* __restrict__ logits,
                                                     const float* __restrict__ labels) {
    const int tid = threadIdx.x;
    const int bid = blockIdx.x;

    if (bid < NN) {
        __shared__ float sx[NN * 65];
        __shared__ float rn[NN];
        for (int t = tid; t < NN * DD; t += 256)
            sx[(t >> 6) * 65 + (t & 63)] = logits[t];
        __syncthreads();
        if (tid < NN) {
            float s = 0.f;
            #pragma unroll
            for (int d = 0; d < DD; d++) { float v = sx[tid * 65 + d]; s += v * v; }
            rn[tid] = rsqrtf(s);
        }
        __syncthreads();
        if (tid < NN) {
            float acc = 0.f;
            #pragma unroll
            for (int d = 0; d < DD; d++) acc += sx[bid * 65 + d] * sx[tid * 65 + d];
            g_mat[bid * NN + tid] = -acc * rn[bid] * rn[tid];
        }
    } else {
        // Label masks: sames_raw[i,j] = (lab_i . lab_j) > 0
        __shared__ float    slab[NN * CC];
        __shared__ unsigned ss[NN * 3], sd[NN * 3];
        for (int t = tid; t < NN * CC; t += 256) slab[t] = labels[t];
        for (int t = tid; t < NN * 3; t += 256) { ss[t] = 0u; sd[t] = 0u; }
        __syncthreads();
        for (int t = tid; t < NN * NN; t += 256) {
            int i = t / NN, j = t - i * NN;
            float acc = 0.f;
            #pragma unroll
            for (int c = 0; c < CC; c++) acc += slab[i * CC + c] * slab[j * CC + c];
            if (acc > 0.f) {
                if (i != j) atomicOr(&ss[i * 3 + (j >> 5)], 1u << (j & 31));
            } else {
                atomicOr(&sd[i * 3 + (j >> 5)], 1u << (j & 31));
            }
        }
        __syncthreads();
        for (int t = tid; t < NN * 3; t += 256) {
            g_smask[t] = ss[t];
            g_dmask[t] = sd[t];
        }
    }
}

// ---------------------------------------------------------------------------
// K2: epsilon (single tiny block; deterministic serial final reduce).
//   num_i = (S-1)*(S*mdsum - msum_s*dsum),  q_i = S*(S-1)/2 * dsum
// ---------------------------------------------------------------------------
__global__ __launch_bounds__(1024) void k2_eps() {
    __shared__ float s_rnum[NN], s_rq[NN];
    const int tid = threadIdx.x, warp = tid >> 5, lane = tid & 31;

    for (int i = warp; i < NN; i += 32) {
        float S = 0.f, ds = 0.f, ms = 0.f, md = 0.f;
        #pragma unroll
        for (int jj = 0; jj < 3; jj++) {
            float mv = g_mat[i * NN + jj * 32 + lane];
            if ((g_smask[i * 3 + jj] >> lane) & 1u) { S += 1.f; ms += mv; }
            if ((g_dmask[i * 3 + jj] >> lane) & 1u) { ds += 1.f; md += mv; }
        }
        #pragma unroll
        for (int o = 16; o; o >>= 1) {
            S  += __shfl_xor_sync(0xffffffffu, S,  o);
            ds += __shfl_xor_sync(0xffffffffu, ds, o);
            ms += __shfl_xor_sync(0xffffffffu, ms, o);
            md += __shfl_xor_sync(0xffffffffu, md, o);
        }
        if (lane == 0) {
            s_rnum[i] = (S - 1.f) * (S * md - ms * ds);
            s_rq[i]   = 0.5f * S * (S - 1.f) * ds;
        }
    }
    __syncthreads();
    if (tid == 0) {
        float num = 0.f, q = 0.f;
        for (int i = 0; i < NN; i++) { num += s_rnum[i]; q += s_rq[i]; }
        float mean_delta = num / fmaxf(2.f * q, 1.f);
        g_eps = fmaxf(mean_delta * 0.5f, 0.f);   // relu(mean_delta / K_DELTA)
    }
}

// ---------------------------------------------------------------------------
// K3: cmask build, one block per anchor i. 32 warps x 3 pair-iterations.
// c[i,p,n] = sames[i,p] & diffs[i,n] & (0 < mat[i,n]-mat[i,p] <= eps)
// ---------------------------------------------------------------------------
__global__ __launch_bounds__(1024) void k3_cmask() {
    __shared__ float    srow[NN];
    __shared__ unsigned sm[3], dm[3];
    const int i = blockIdx.x;
    const int tid = threadIdx.x, warp = tid >> 5, lane = tid & 31;

    if (tid < NN) srow[tid] = g_mat[i * NN + tid];
    if (tid < 3) { sm[tid] = g_smask[i * 3 + tid]; dm[tid] = g_dmask[i * 3 + tid]; }
    __syncthreads();
    const float eps = g_eps;

    for (int p = warp; p < NN; p += 32) {
        unsigned sp = (sm[p >> 5] >> (p & 31)) & 1u;
        float matp = srow[p];
        #pragma unroll
        for (int wd = 0; wd < 3; wd++) {
            float m = srow[wd * 32 + lane] - matp;
            bool cc = sp && (((dm[wd] >> lane) & 1u) != 0u) && (m > 0.f) && (m <= eps);
            unsigned b = __ballot_sync(0xffffffffu, cc);
            if (lane == 0) g_cmask[(i * NN + p) * 4 + wd] = b;
        }
    }
}

// ---------------------------------------------------------------------------
// K4: the 340 MB writer. One block per (i,j). Precompute the 96x3 AND-ed
// words (cmask[i,j] & cmask[i,k], zeroed for k<=j) into smem; then each of
// 256 threads emits 9 coalesced float4 (4 n-bits each) from LDS.
// ---------------------------------------------------------------------------
__global__ __launch_bounds__(256) void k4_write(float4* __restrict__ out) {
    __shared__ unsigned sw[NN * 3];
    const int r2 = blockIdx.x;           // i*96 + j
    const int j  = r2 % NN;
    const int ibase = r2 - j;            // i*96
    const int tid = threadIdx.x;

    for (int t = tid; t < NN * 3; t += 256) {
        int k  = t / 3;
        int wd = t - k * 3;
        unsigned v = 0u;
        if (k > j)
            v = g_cmask[(r2 << 2) + wd] & g_cmask[((ibase + k) << 2) + wd];
        sw[t] = v;                       // layout sw[k*3 + wd]
    }
    __syncthreads();

    float4* o = out + (size_t)r2 * 2304; // 96*96/4 float4 per (i,j)
    const unsigned ONEF = 0x3f800000u;
    #pragma unroll
    for (int p = 0; p < 9; p++) {
        int pos = p * 256 + tid;         // 0..2303
        int k   = pos / 24;              // 24 float4 per n-row
        int n4  = pos - k * 24;
        unsigned w = sw[k * 3 + (n4 >> 3)];
        unsigned b = w >> ((n4 & 7) * 4);
        float4 v;
        v.x = __uint_as_float(ONEF & (0u - (b & 1u)));
        v.y = __uint_as_float(ONEF & (0u - ((b >> 1) & 1u)));
        v.z = __uint_as_float(ONEF & (0u - ((b >> 2) & 1u)));
        v.w = __uint_as_float(ONEF & (0u - ((b >> 3) & 1u)));
        o[pos] = v;
    }
}

// ---------------------------------------------------------------------------
extern "C" void kernel_launch(void* const* d_in, const int* in_sizes, int n_in,
                              void* d_out, int out_size) {
    const float* logits = (const float*)d_in[0];   // [96,64]
    const float* labels = (const float*)d_in[1];   // [96,30]

    k1_mat_labels<<<NN + 1, 256>>>(logits, labels);
    k2_eps<<<1, 1024>>>();
    k3_cmask<<<NN, 1024>>>();
    k4_write<<<NN * NN, 256>>>((float4*)d_out);
}

// round 3
// speedup vs baseline: 2.3778x; 1.0954x over previous
#include <cuda_runtime.h>
#include <cuda_bf16.h>
#include <stdint.h>

#define NN 96
#define DD 64
#define CC 30

// Scratch (__device__ globals; no allocation allowed)
__device__ float    g_mat[NN * NN];
__device__ unsigned g_smask[NN * 3];
__device__ unsigned g_dmask[NN * 3];
__device__ unsigned g_cmask[NN * NN * 4];   // 96-bit mask per (i,p), stride 4 words

// ---------------------------------------------------------------------------
// kA: blocks 0..95 -> cosine mat row i ; block 96 -> label masks.
// ---------------------------------------------------------------------------
__global__ __launch_bounds__(256) void kA_mat_labels(const float* __restrict__ logits,
                                                     const float* __restrict__ labels) {
    const int tid = threadIdx.x;
    const int bid = blockIdx.x;

    if (bid < NN) {
        __shared__ float sx[NN * 65];
        __shared__ float rn[NN];
        for (int t = tid; t < NN * DD; t += 256)
            sx[(t >> 6) * 65 + (t & 63)] = logits[t];
        __syncthreads();
        if (tid < NN) {
            float s = 0.f;
            #pragma unroll
            for (int d = 0; d < DD; d++) { float v = sx[tid * 65 + d]; s += v * v; }
            rn[tid] = rsqrtf(s);
        }
        __syncthreads();
        if (tid < NN) {
            float acc = 0.f;
            #pragma unroll
            for (int d = 0; d < DD; d++) acc += sx[bid * 65 + d] * sx[tid * 65 + d];
            g_mat[bid * NN + tid] = -acc * rn[bid] * rn[tid];
        }
    } else {
        // Label masks: sames_raw[i,j] = (lab_i . lab_j) > 0
        __shared__ float    slab[NN * CC];
        __shared__ unsigned ss[NN * 3], sd[NN * 3];
        for (int t = tid; t < NN * CC; t += 256) slab[t] = labels[t];
        for (int t = tid; t < NN * 3; t += 256) { ss[t] = 0u; sd[t] = 0u; }
        __syncthreads();
        for (int t = tid; t < NN * NN; t += 256) {
            int i = t / NN, j = t - i * NN;
            float acc = 0.f;
            #pragma unroll
            for (int c = 0; c < CC; c++) acc += slab[i * CC + c] * slab[j * CC + c];
            if (acc > 0.f) {
                if (i != j) atomicOr(&ss[i * 3 + (j >> 5)], 1u << (j & 31));
            } else {
                atomicOr(&sd[i * 3 + (j >> 5)], 1u << (j & 31));
            }
        }
        __syncthreads();
        for (int t = tid; t < NN * 3; t += 256) {
            g_smask[t] = ss[t];
            g_dmask[t] = sd[t];
        }
    }
}

// ---------------------------------------------------------------------------
// kB: one block per anchor i. Each block FIRST computes epsilon redundantly
// (bit-identical order to the reference serial reduce -> same eps in every
// block, deterministic), then builds the 96-bit c-mask for its anchor.
// ---------------------------------------------------------------------------
__global__ __launch_bounds__(1024) void kB_eps_cmask() {
    __shared__ float    s_rnum[NN], s_rq[NN];
    __shared__ float    s_eps;
    __shared__ float    srow[NN];
    __shared__ unsigned sm[3], dm[3];

    const int ianc = blockIdx.x;
    const int tid  = threadIdx.x, warp = tid >> 5, lane = tid & 31;

    // ---- epsilon (same math/order as before) ----
    for (int i = warp; i < NN; i += 32) {
        float S = 0.f, ds = 0.f, ms = 0.f, md = 0.f;
        #pragma unroll
        for (int jj = 0; jj < 3; jj++) {
            float mv = g_mat[i * NN + jj * 32 + lane];
            if ((g_smask[i * 3 + jj] >> lane) & 1u) { S += 1.f; ms += mv; }
            if ((g_dmask[i * 3 + jj] >> lane) & 1u) { ds += 1.f; md += mv; }
        }
        #pragma unroll
        for (int o = 16; o; o >>= 1) {
            S  += __shfl_xor_sync(0xffffffffu, S,  o);
            ds += __shfl_xor_sync(0xffffffffu, ds, o);
            ms += __shfl_xor_sync(0xffffffffu, ms, o);
            md += __shfl_xor_sync(0xffffffffu, md, o);
        }
        if (lane == 0) {
            s_rnum[i] = (S - 1.f) * (S * md - ms * ds);
            s_rq[i]   = 0.5f * S * (S - 1.f) * ds;
        }
    }
    // load this anchor's data while waiting
    if (tid < NN) srow[tid] = g_mat[ianc * NN + tid];
    if (tid >= NN && tid < NN + 3) {
        sm[tid - NN] = g_smask[ianc * 3 + (tid - NN)];
        dm[tid - NN] = g_dmask[ianc * 3 + (tid - NN)];
    }
    __syncthreads();
    if (tid == 0) {   // serial reduce: identical order to previous passing kernel
        float num = 0.f, q = 0.f;
        for (int i = 0; i < NN; i++) { num += s_rnum[i]; q += s_rq[i]; }
        float mean_delta = num / fmaxf(2.f * q, 1.f);
        s_eps = fmaxf(mean_delta * 0.5f, 0.f);   // relu(mean_delta / K_DELTA)
    }
    __syncthreads();
    const float eps = s_eps;

    // ---- cmask for anchor ianc ----
    for (int p = warp; p < NN; p += 32) {
        unsigned sp = (sm[p >> 5] >> (p & 31)) & 1u;
        float matp = srow[p];
        #pragma unroll
        for (int wd = 0; wd < 3; wd++) {
            float m = srow[wd * 32 + lane] - matp;
            bool cc = sp && (((dm[wd] >> lane) & 1u) != 0u) && (m > 0.f) && (m <= eps);
            unsigned b = __ballot_sync(0xffffffffu, cc);
            if (lane == 0) g_cmask[(ianc * NN + p) * 4 + wd] = b;
        }
    }
}

// ---------------------------------------------------------------------------
// kC: the 340 MB writer. One block per (i,j). Precompute the 96x3 AND-ed
// words into smem; each of 256 threads emits 9 coalesced float4 via
// streaming stores (output >> L2, evict-first).
// ---------------------------------------------------------------------------
__global__ __launch_bounds__(256) void kC_write(float4* __restrict__ out) {
    __shared__ unsigned sw[NN * 3];
    const int r2 = blockIdx.x;           // i*96 + j
    const int j  = r2 % NN;
    const int ibase = r2 - j;            // i*96
    const int tid = threadIdx.x;

    for (int t = tid; t < NN * 3; t += 256) {
        int k  = t / 3;
        int wd = t - k * 3;
        unsigned v = 0u;
        if (k > j)
            v = g_cmask[(r2 << 2) + wd] & g_cmask[((ibase + k) << 2) + wd];
        sw[t] = v;                       // layout sw[k*3 + wd]
    }
    __syncthreads();

    float4* o = out + (size_t)r2 * 2304; // 96*96/4 float4 per (i,j)
    const unsigned ONEF = 0x3f800000u;
    #pragma unroll
    for (int p = 0; p < 9; p++) {
        int pos = p * 256 + tid;         // 0..2303
        int k   = pos / 24;              // 24 float4 per n-row
        int n4  = pos - k * 24;
        unsigned w = sw[k * 3 + (n4 >> 3)];
        unsigned b = w >> ((n4 & 7) * 4);
        float4 v;
        v.x = __uint_as_float(ONEF & (0u - (b & 1u)));
        v.y = __uint_as_float(ONEF & (0u - ((b >> 1) & 1u)));
        v.z = __uint_as_float(ONEF & (0u - ((b >> 2) & 1u)));
        v.w = __uint_as_float(ONEF & (0u - ((b >> 3) & 1u)));
        __stcs(&o[pos], v);              // streaming store: evict-first
    }
}

// ---------------------------------------------------------------------------
extern "C" void kernel_launch(void* const* d_in, const int* in_sizes, int n_in,
                              void* d_out, int out_size) {
    const float* logits = (const float*)d_in[0];   // [96,64]
    const float* labels = (const float*)d_in[1];   // [96,30]

    kA_mat_labels<<<NN + 1, 256>>>(logits, labels);
    kB_eps_cmask<<<NN, 1024>>>();
    kC_write<<<NN * NN, 256>>>((float4*)d_out);
}

// round 4
// speedup vs baseline: 2.7987x; 1.1770x over previous
#include <cuda_runtime.h>
#include <cuda_bf16.h>
#include <stdint.h>

#define NN 96
#define DD 64
#define CC 30

// Scratch (__device__ globals; no allocation allowed)
__device__ float    g_mat[NN * NN];
__device__ unsigned g_smask[NN * 3];
__device__ unsigned g_dmask[NN * 3];
__device__ unsigned g_cmask[NN * NN * 4];   // 96-bit mask per (i,p), stride 4 words

// ---------------------------------------------------------------------------
// kA: 12 blocks x 1024 threads.
//   blocks 0..8  : cosine mat, ONE OUTPUT PER THREAD (9*1024 = 96*96).
//                  96 = 3*32 so each warp stays inside one row: LHS row is a
//                  broadcast LDS, RHS is stride-65 conflict-free.
//   blocks 9..11 : label masks, one WARP per row i, bits built with ballots
//                  (no atomics, no div/mod in the hot path).
// ---------------------------------------------------------------------------
__global__ __launch_bounds__(1024) void kA_mat_labels(const float* __restrict__ logits,
                                                      const float* __restrict__ labels) {
    const int tid = threadIdx.x;
    const int bid = blockIdx.x;

    if (bid < 9) {
        __shared__ float sx[NN * 65];
        __shared__ float rn[NN];
        #pragma unroll
        for (int it = 0; it < 6; it++) {
            int t = it * 1024 + tid;                  // 6144 = 96*64
            sx[(t >> 6) * 65 + (t & 63)] = logits[t];
        }
        __syncthreads();
        if (tid < NN) {                               // norms (same order as before)
            float s = 0.f;
            #pragma unroll
            for (int d = 0; d < DD; d++) { float v = sx[tid * 65 + d]; s += v * v; }
            rn[tid] = rsqrtf(s);
        }
        __syncthreads();
        const int outp = bid * 1024 + tid;            // 0..9215
        const int r = outp / NN;                      // warp-uniform (96 = 3 warps)
        const int c = outp - r * NN;
        float acc = 0.f;
        #pragma unroll
        for (int d = 0; d < DD; d++) acc += sx[r * 65 + d] * sx[c * 65 + d];
        g_mat[outp] = -acc * rn[r] * rn[c];
    } else {
        __shared__ float slab[NN * CC];
        #pragma unroll
        for (int it = 0; it < 3; it++) {
            int t = it * 1024 + tid;                  // 2880 = 96*30
            if (t < NN * CC) slab[t] = labels[t];
        }
        __syncthreads();
        const int warp = tid >> 5, lane = tid & 31;
        const int i = (bid - 9) * 32 + warp;          // row 0..95
        #pragma unroll
        for (int wd = 0; wd < 3; wd++) {
            int j = wd * 32 + lane;
            float acc = 0.f;
            #pragma unroll
            for (int cc = 0; cc < CC; cc++) acc += slab[i * CC + cc] * slab[j * CC + cc];
            bool same_raw = acc > 0.f;
            unsigned sb = __ballot_sync(0xffffffffu, same_raw && (j != i));
            unsigned db = __ballot_sync(0xffffffffu, !same_raw);
            if (lane == 0) {
                g_smask[i * 3 + wd] = sb;
                g_dmask[i * 3 + wd] = db;
            }
        }
    }
}

// ---------------------------------------------------------------------------
// kB: one block per anchor i. Each block computes epsilon redundantly
// (bit-identical order in every block -> deterministic), then builds the
// 96-bit c-mask for its anchor.
// ---------------------------------------------------------------------------
__global__ __launch_bounds__(1024) void kB_eps_cmask() {
    __shared__ float    s_rnum[NN], s_rq[NN];
    __shared__ float    s_eps;
    __shared__ float    srow[NN];
    __shared__ unsigned sm[3], dm[3];

    const int ianc = blockIdx.x;
    const int tid  = threadIdx.x, warp = tid >> 5, lane = tid & 31;

    // ---- epsilon ----
    for (int i = warp; i < NN; i += 32) {
        float S = 0.f, ds = 0.f, ms = 0.f, md = 0.f;
        #pragma unroll
        for (int jj = 0; jj < 3; jj++) {
            float mv = g_mat[i * NN + jj * 32 + lane];
            if ((g_smask[i * 3 + jj] >> lane) & 1u) { S += 1.f; ms += mv; }
            if ((g_dmask[i * 3 + jj] >> lane) & 1u) { ds += 1.f; md += mv; }
        }
        #pragma unroll
        for (int o = 16; o; o >>= 1) {
            S  += __shfl_xor_sync(0xffffffffu, S,  o);
            ds += __shfl_xor_sync(0xffffffffu, ds, o);
            ms += __shfl_xor_sync(0xffffffffu, ms, o);
            md += __shfl_xor_sync(0xffffffffu, md, o);
        }
        if (lane == 0) {
            s_rnum[i] = (S - 1.f) * (S * md - ms * ds);
            s_rq[i]   = 0.5f * S * (S - 1.f) * ds;
        }
    }
    if (tid < NN) srow[tid] = g_mat[ianc * NN + tid];
    if (tid >= NN && tid < NN + 3) {
        sm[tid - NN] = g_smask[ianc * 3 + (tid - NN)];
        dm[tid - NN] = g_dmask[ianc * 3 + (tid - NN)];
    }
    __syncthreads();
    if (tid == 0) {   // serial reduce: identical order every block
        float num = 0.f, q = 0.f;
        for (int i = 0; i < NN; i++) { num += s_rnum[i]; q += s_rq[i]; }
        float mean_delta = num / fmaxf(2.f * q, 1.f);
        s_eps = fmaxf(mean_delta * 0.5f, 0.f);   // relu(mean_delta / K_DELTA)
    }
    __syncthreads();
    const float eps = s_eps;

    // ---- cmask for anchor ianc ----
    for (int p = warp; p < NN; p += 32) {
        unsigned sp = (sm[p >> 5] >> (p & 31)) & 1u;
        float matp = srow[p];
        #pragma unroll
        for (int wd = 0; wd < 3; wd++) {
            float m = srow[wd * 32 + lane] - matp;
            bool cc = sp && (((dm[wd] >> lane) & 1u) != 0u) && (m > 0.f) && (m <= eps);
            unsigned b = __ballot_sync(0xffffffffu, cc);
            if (lane == 0) g_cmask[(ianc * NN + p) * 4 + wd] = b;
        }
    }
}

// ---------------------------------------------------------------------------
// kC: the 340 MB writer. One block per (i,j). Precompute the 96x3 AND-ed
// words into smem; each of 256 threads emits 9 coalesced float4 via
// streaming stores (output >> L2, evict-first).
// ---------------------------------------------------------------------------
__global__ __launch_bounds__(256) void kC_write(float4* __restrict__ out) {
    __shared__ unsigned sw[NN * 3];
    const int r2 = blockIdx.x;           // i*96 + j
    const int j  = r2 % NN;
    const int ibase = r2 - j;            // i*96
    const int tid = threadIdx.x;

    for (int t = tid; t < NN * 3; t += 256) {
        int k  = t / 3;
        int wd = t - k * 3;
        unsigned v = 0u;
        if (k > j)
            v = g_cmask[(r2 << 2) + wd] & g_cmask[((ibase + k) << 2) + wd];
        sw[t] = v;                       // layout sw[k*3 + wd]
    }
    __syncthreads();

    float4* o = out + (size_t)r2 * 2304; // 96*96/4 float4 per (i,j)
    const unsigned ONEF = 0x3f800000u;
    #pragma unroll
    for (int p = 0; p < 9; p++) {
        int pos = p * 256 + tid;         // 0..2303
        int k   = pos / 24;              // 24 float4 per n-row
        int n4  = pos - k * 24;
        unsigned w = sw[k * 3 + (n4 >> 3)];
        unsigned b = w >> ((n4 & 7) * 4);
        float4 v;
        v.x = __uint_as_float(ONEF & (0u - (b & 1u)));
        v.y = __uint_as_float(ONEF & (0u - ((b >> 1) & 1u)));
        v.z = __uint_as_float(ONEF & (0u - ((b >> 2) & 1u)));
        v.w = __uint_as_float(ONEF & (0u - ((b >> 3) & 1u)));
        __stcs(&o[pos], v);              // streaming store: evict-first
    }
}

// ---------------------------------------------------------------------------
extern "C" void kernel_launch(void* const* d_in, const int* in_sizes, int n_in,
                              void* d_out, int out_size) {
    const float* logits = (const float*)d_in[0];   // [96,64]
    const float* labels = (const float*)d_in[1];   // [96,30]

    kA_mat_labels<<<12, 1024>>>(logits, labels);
    kB_eps_cmask<<<NN, 1024>>>();
    kC_write<<<NN * NN, 256>>>((float4*)d_out);
}